// round 6
// baseline (speedup 1.0000x reference)
#include <cuda_runtime.h>
#include <cuda_bf16.h>
#include <math.h>

#define BB 64
#define TT 128
#define DD 64
#define HH 512
#define VV 16000
#define GG 2048           // 4*H
#define BT (BB*TT)        // 8192
#define HS (HH*BB)        // one h/c state buffer: 512*64 = 32768 floats

// ---------------- device scratch (allocation-free, static globals) --------
__device__ float g_x  [BT*DD];        // embeddings, row-major [r=b*T+t][D]   (2 MB)
__device__ float g_xg [TT*GG*BB];     // gate pre-acts, t-major [t][4H][b]    (64 MB)
__device__ float g_y  [BT*HH];        // layer output seq, row-major [r][H]   (16 MB)
__device__ float g_h  [2*HS];         // h double buffer, transposed [k][b]   (256 KB)
__device__ float g_c  [HS];           // c state, transposed [k][b]           (128 KB)
__device__ float g_hf [2*HS];         // encoder final h per layer
__device__ float g_cf [2*HS];         // encoder final c per layer

// ---------------- embedding gather ----------------------------------------
__global__ void gather_kernel(const int* __restrict__ batch,
                              const float* __restrict__ feat,
                              float* __restrict__ x)
{
    int r = blockIdx.x * 4 + (threadIdx.x >> 6);
    int d = threadIdx.x & 63;
    x[r * DD + d] = feat[batch[r] * DD + d];
}

// ---------------- SGEMM: C = A[M,K] * B[N,K]^T + bias1[n] + bias2[n] ------
// 128x128 tile, BK=16, 256 threads, 8x8 microtile, double-buffered smem.
// scatter==0: C row-major [M,N].
// scatter==1: C[((m%T)*GG + n)*BB + m/T]  (t-major gate layout for the scan)
__global__ void __launch_bounds__(256) sgemm128(
    const float* __restrict__ A, const float* __restrict__ B,
    float* __restrict__ C,
    const float* __restrict__ bias1, const float* __restrict__ bias2,
    int M, int N, int K, int scatter)
{
    __shared__ float As[2][16][128];
    __shared__ float Bs[2][16][128];
    int tid = threadIdx.x;
    int m0 = blockIdx.y * 128;
    int n0 = blockIdx.x * 128;

    int lr = tid >> 2;            // 0..63
    int lc = (tid & 3) << 2;      // 0,4,8,12
    const float* Aload = A + (size_t)(m0 + lr) * K + lc;
    const float* Bload = B + (size_t)(n0 + lr) * K + lc;

    // preload k-tile 0
    float4 a0 = *(const float4*)(Aload);
    float4 a1 = *(const float4*)(Aload + (size_t)64 * K);
    float4 b0 = *(const float4*)(Bload);
    float4 b1 = *(const float4*)(Bload + (size_t)64 * K);
    As[0][lc+0][lr] = a0.x; As[0][lc+1][lr] = a0.y; As[0][lc+2][lr] = a0.z; As[0][lc+3][lr] = a0.w;
    As[0][lc+0][lr+64] = a1.x; As[0][lc+1][lr+64] = a1.y; As[0][lc+2][lr+64] = a1.z; As[0][lc+3][lr+64] = a1.w;
    Bs[0][lc+0][lr] = b0.x; Bs[0][lc+1][lr] = b0.y; Bs[0][lc+2][lr] = b0.z; Bs[0][lc+3][lr] = b0.w;
    Bs[0][lc+0][lr+64] = b1.x; Bs[0][lc+1][lr+64] = b1.y; Bs[0][lc+2][lr+64] = b1.z; Bs[0][lc+3][lr+64] = b1.w;
    __syncthreads();

    int tx = tid & 15, ty = tid >> 4;
    float acc[8][8];
    #pragma unroll
    for (int i = 0; i < 8; i++)
        #pragma unroll
        for (int j = 0; j < 8; j++) acc[i][j] = 0.f;

    int nk = K >> 4;
    for (int kt = 0; kt < nk; kt++) {
        int cur = kt & 1;
        float4 na0, na1, nb0, nb1;
        bool has_next = (kt + 1 < nk);
        if (has_next) {
            const float* Ap = Aload + (kt + 1) * 16;
            const float* Bp = Bload + (kt + 1) * 16;
            na0 = *(const float4*)(Ap);
            na1 = *(const float4*)(Ap + (size_t)64 * K);
            nb0 = *(const float4*)(Bp);
            nb1 = *(const float4*)(Bp + (size_t)64 * K);
        }
        #pragma unroll
        for (int k = 0; k < 16; k++) {
            float a[8], b[8];
            *(float4*)(a)     = *(const float4*)&As[cur][k][ty * 8];
            *(float4*)(a + 4) = *(const float4*)&As[cur][k][ty * 8 + 4];
            *(float4*)(b)     = *(const float4*)&Bs[cur][k][tx * 8];
            *(float4*)(b + 4) = *(const float4*)&Bs[cur][k][tx * 8 + 4];
            #pragma unroll
            for (int i = 0; i < 8; i++)
                #pragma unroll
                for (int j = 0; j < 8; j++)
                    acc[i][j] = fmaf(a[i], b[j], acc[i][j]);
        }
        if (has_next) {
            int nxt = cur ^ 1;
            As[nxt][lc+0][lr] = na0.x; As[nxt][lc+1][lr] = na0.y; As[nxt][lc+2][lr] = na0.z; As[nxt][lc+3][lr] = na0.w;
            As[nxt][lc+0][lr+64] = na1.x; As[nxt][lc+1][lr+64] = na1.y; As[nxt][lc+2][lr+64] = na1.z; As[nxt][lc+3][lr+64] = na1.w;
            Bs[nxt][lc+0][lr] = nb0.x; Bs[nxt][lc+1][lr] = nb0.y; Bs[nxt][lc+2][lr] = nb0.z; Bs[nxt][lc+3][lr] = nb0.w;
            Bs[nxt][lc+0][lr+64] = nb1.x; Bs[nxt][lc+1][lr+64] = nb1.y; Bs[nxt][lc+2][lr+64] = nb1.z; Bs[nxt][lc+3][lr+64] = nb1.w;
            __syncthreads();
        }
    }

    // epilogue
    float bcol[8];
    #pragma unroll
    for (int j = 0; j < 8; j++) {
        int n = n0 + tx * 8 + j;
        float bb = 0.f;
        if (bias1) bb += bias1[n];
        if (bias2) bb += bias2[n];
        bcol[j] = bb;
    }
    if (scatter == 0) {
        #pragma unroll
        for (int i = 0; i < 8; i++) {
            int m = m0 + ty * 8 + i;
            float* Crow = C + (size_t)m * N + n0 + tx * 8;
            float4 v0, v1;
            v0.x = acc[i][0] + bcol[0]; v0.y = acc[i][1] + bcol[1];
            v0.z = acc[i][2] + bcol[2]; v0.w = acc[i][3] + bcol[3];
            v1.x = acc[i][4] + bcol[4]; v1.y = acc[i][5] + bcol[5];
            v1.z = acc[i][6] + bcol[6]; v1.w = acc[i][7] + bcol[7];
            *(float4*)(Crow)     = v0;
            *(float4*)(Crow + 4) = v1;
        }
    } else {
        #pragma unroll
        for (int i = 0; i < 8; i++) {
            int m = m0 + ty * 8 + i;
            int t = m & (TT - 1);
            int b = m >> 7;          // T = 128
            #pragma unroll
            for (int j = 0; j < 8; j++) {
                int n = n0 + tx * 8 + j;
                C[((size_t)t * GG + n) * BB + b] = acc[i][j] + bcol[j];
            }
        }
    }
}

// ---------------- LSTM step kernel ----------------------------------------
// grid = 128 CTAs (4 hidden units each), 256 threads.
// h stored transposed [k][b]; xg t-major [t][4H][b]; y row-major [b*T+t][H].
__global__ void __launch_bounds__(256) lstm_step(
    const float* __restrict__ xg, const float* __restrict__ Whh,
    const float* __restrict__ h_prev, float* __restrict__ h_next,
    float* __restrict__ c, float* __restrict__ y, int t)
{
    __shared__ float ws[16][HH];       // 16 Whh rows (4 units x 4 gates), 32 KB
    int tid = threadIdx.x;
    int jj0 = blockIdx.x << 2;

    // cooperative load of the 16 needed Whh rows (float4, coalesced)
    for (int i = tid; i < 16 * (HH / 4); i += 256) {
        int rowi = i >> 7;             // 0..15 (HH/4 = 128 float4 per row)
        int c4 = i & 127;
        int g = rowi >> 2, dd = rowi & 3;
        ((float4*)ws[rowi])[c4] =
            ((const float4*)(Whh + (size_t)(jj0 + dd + HH * g) * HH))[c4];
    }
    __syncthreads();

    int b = tid & 63;
    int d = tid >> 6;                  // 0..3
    const float* ws0 = ws[d];
    const float* ws1 = ws[4 + d];
    const float* ws2 = ws[8 + d];
    const float* ws3 = ws[12 + d];

    float a0 = 0.f, a1 = 0.f, a2 = 0.f, a3 = 0.f;
    #pragma unroll 2
    for (int k = 0; k < HH; k += 4) {
        float4 w0 = *(const float4*)&ws0[k];
        float4 w1 = *(const float4*)&ws1[k];
        float4 w2 = *(const float4*)&ws2[k];
        float4 w3 = *(const float4*)&ws3[k];
        float h0 = h_prev[(k + 0) * BB + b];
        float h1 = h_prev[(k + 1) * BB + b];
        float h2 = h_prev[(k + 2) * BB + b];
        float h3 = h_prev[(k + 3) * BB + b];
        a0 = fmaf(h0, w0.x, a0); a0 = fmaf(h1, w0.y, a0); a0 = fmaf(h2, w0.z, a0); a0 = fmaf(h3, w0.w, a0);
        a1 = fmaf(h0, w1.x, a1); a1 = fmaf(h1, w1.y, a1); a1 = fmaf(h2, w1.z, a1); a1 = fmaf(h3, w1.w, a1);
        a2 = fmaf(h0, w2.x, a2); a2 = fmaf(h1, w2.y, a2); a2 = fmaf(h2, w2.z, a2); a2 = fmaf(h3, w2.w, a2);
        a3 = fmaf(h0, w3.x, a3); a3 = fmaf(h1, w3.y, a3); a3 = fmaf(h2, w3.z, a3); a3 = fmaf(h3, w3.w, a3);
    }

    int jj = jj0 + d;
    const float* xgt = xg + (size_t)t * GG * BB + b;
    float xi = xgt[(size_t)(jj         ) * BB];
    float xf = xgt[(size_t)(jj + HH    ) * BB];
    float xgg= xgt[(size_t)(jj + 2 * HH) * BB];
    float xo = xgt[(size_t)(jj + 3 * HH) * BB];

    float gi = 1.f / (1.f + expf(-(a0 + xi)));
    float gf = 1.f / (1.f + expf(-(a1 + xf)));
    float gg = tanhf(a2 + xgg);
    float go = 1.f / (1.f + expf(-(a3 + xo)));

    int idx = jj * BB + b;
    float cv = gf * c[idx] + gi * gg;
    c[idx] = cv;
    float hv = go * tanhf(cv);
    h_next[idx] = hv;
    y[((size_t)b * TT + t) * HH + jj] = hv;
}

// ---------------- row softmax (in-place, row buffered in dyn smem) --------
__global__ void __launch_bounds__(256) softmax_kernel(float* __restrict__ P, int N)
{
    extern __shared__ float row[];
    __shared__ float red[8];
    int tid = threadIdx.x;
    float* p = P + (size_t)blockIdx.x * N;

    float mx = -3.4e38f;
    for (int i = tid * 4; i < N; i += 1024) {
        float4 v = *(const float4*)(p + i);
        *(float4*)(row + i) = v;
        mx = fmaxf(mx, fmaxf(fmaxf(v.x, v.y), fmaxf(v.z, v.w)));
    }
    #pragma unroll
    for (int o = 16; o; o >>= 1) mx = fmaxf(mx, __shfl_xor_sync(0xffffffffu, mx, o));
    if ((tid & 31) == 0) red[tid >> 5] = mx;
    __syncthreads();
    float m = red[0];
    #pragma unroll
    for (int w = 1; w < 8; w++) m = fmaxf(m, red[w]);
    __syncthreads();

    float sum = 0.f;
    for (int i = tid * 4; i < N; i += 1024) {
        float4 v = *(float4*)(row + i);
        v.x = expf(v.x - m); v.y = expf(v.y - m);
        v.z = expf(v.z - m); v.w = expf(v.w - m);
        sum += (v.x + v.y) + (v.z + v.w);
        *(float4*)(row + i) = v;
    }
    #pragma unroll
    for (int o = 16; o; o >>= 1) sum += __shfl_xor_sync(0xffffffffu, sum, o);
    if ((tid & 31) == 0) red[tid >> 5] = sum;
    __syncthreads();
    float tot = 0.f;
    #pragma unroll
    for (int w = 0; w < 8; w++) tot += red[w];
    float inv = 1.f / tot;

    for (int i = tid * 4; i < N; i += 1024) {
        float4 v = *(float4*)(row + i);
        v.x *= inv; v.y *= inv; v.z *= inv; v.w *= inv;
        *(float4*)(p + i) = v;
    }
}

// ---------------- host orchestration --------------------------------------
static void run_scan(float* gxg, const float* Whh, float* gh, float* gc, float* gy)
{
    for (int t = 0; t < TT; t++) {
        lstm_step<<<HH / 4, 256>>>(gxg, Whh,
                                   gh + (t & 1) * HS, gh + ((t + 1) & 1) * HS,
                                   gc, gy, t);
    }
}

extern "C" void kernel_launch(void* const* d_in, const int* in_sizes, int n_in,
                              void* d_out, int out_size)
{
    const int*   batch    = (const int*)d_in[0];
    const float* features = (const float*)d_in[1];
    const float* eWih0 = (const float*)d_in[2];
    const float* eWhh0 = (const float*)d_in[3];
    const float* ebih0 = (const float*)d_in[4];
    const float* ebhh0 = (const float*)d_in[5];
    const float* eWih1 = (const float*)d_in[6];
    const float* eWhh1 = (const float*)d_in[7];
    const float* ebih1 = (const float*)d_in[8];
    const float* ebhh1 = (const float*)d_in[9];
    const float* dWih0 = (const float*)d_in[10];
    const float* dWhh0 = (const float*)d_in[11];
    const float* dbih0 = (const float*)d_in[12];
    const float* dbhh0 = (const float*)d_in[13];
    const float* dWih1 = (const float*)d_in[14];
    const float* dWhh1 = (const float*)d_in[15];
    const float* dbih1 = (const float*)d_in[16];
    const float* dbhh1 = (const float*)d_in[17];
    const float* linW  = (const float*)d_in[18];
    const float* linb  = (const float*)d_in[19];
    float* out = (float*)d_out;

    float *gx, *gxg, *gy, *gh, *gc, *ghf, *gcf;
    cudaGetSymbolAddress((void**)&gx,  g_x);
    cudaGetSymbolAddress((void**)&gxg, g_xg);
    cudaGetSymbolAddress((void**)&gy,  g_y);
    cudaGetSymbolAddress((void**)&gh,  g_h);
    cudaGetSymbolAddress((void**)&gc,  g_c);
    cudaGetSymbolAddress((void**)&ghf, g_hf);
    cudaGetSymbolAddress((void**)&gcf, g_cf);

    cudaFuncSetAttribute(softmax_kernel,
                         cudaFuncAttributeMaxDynamicSharedMemorySize, VV * 4);

    // 1) embedding gather
    gather_kernel<<<BT / 4, 256>>>(batch, features, gx);

    dim3 gridG(GG / 128, BT / 128);     // xg GEMMs: [8192 x 2048]
    dim3 gridL(VV / 128, BT / 128);     // logits GEMM: [8192 x 16000]

    // ---- encoder layer 0 ----
    sgemm128<<<gridG, 256>>>(gx, eWih0, gxg, ebih0, ebhh0, BT, GG, DD, 1);
    cudaMemsetAsync(gh, 0, HS * sizeof(float), 0);
    cudaMemsetAsync(gc, 0, HS * sizeof(float), 0);
    run_scan(gxg, eWhh0, gh, gc, gy);
    cudaMemcpyAsync(ghf,      gh, HS * sizeof(float), cudaMemcpyDeviceToDevice, 0);
    cudaMemcpyAsync(gcf,      gc, HS * sizeof(float), cudaMemcpyDeviceToDevice, 0);

    // ---- encoder layer 1 ----
    sgemm128<<<gridG, 256>>>(gy, eWih1, gxg, ebih1, ebhh1, BT, GG, HH, 1);
    cudaMemsetAsync(gh, 0, HS * sizeof(float), 0);
    cudaMemsetAsync(gc, 0, HS * sizeof(float), 0);
    run_scan(gxg, eWhh1, gh, gc, gy);
    cudaMemcpyAsync(ghf + HS, gh, HS * sizeof(float), cudaMemcpyDeviceToDevice, 0);
    cudaMemcpyAsync(gcf + HS, gc, HS * sizeof(float), cudaMemcpyDeviceToDevice, 0);

    // ---- decoder layer 0 (init from encoder layer-0 finals) ----
    sgemm128<<<gridG, 256>>>(gx, dWih0, gxg, dbih0, dbhh0, BT, GG, DD, 1);
    cudaMemcpyAsync(gh, ghf,      HS * sizeof(float), cudaMemcpyDeviceToDevice, 0);
    cudaMemcpyAsync(gc, gcf,      HS * sizeof(float), cudaMemcpyDeviceToDevice, 0);
    run_scan(gxg, dWhh0, gh, gc, gy);

    // ---- decoder layer 1 (init from encoder layer-1 finals) ----
    sgemm128<<<gridG, 256>>>(gy, dWih1, gxg, dbih1, dbhh1, BT, GG, HH, 1);
    cudaMemcpyAsync(gh, ghf + HS, HS * sizeof(float), cudaMemcpyDeviceToDevice, 0);
    cudaMemcpyAsync(gc, gcf + HS, HS * sizeof(float), cudaMemcpyDeviceToDevice, 0);
    run_scan(gxg, dWhh1, gh, gc, gy);

    // ---- logits + softmax ----
    sgemm128<<<gridL, 256>>>(gy, linW, out, linb, (const float*)0, BT, VV, HH, 0);
    softmax_kernel<<<BT, 256, VV * 4>>>(out, VV);

    (void)in_sizes; (void)n_in; (void)out_size;
}

// round 8
// speedup vs baseline: 1.1155x; 1.1155x over previous
#include <cuda_runtime.h>
#include <cuda_bf16.h>
#include <math.h>

#define BB 64
#define TT 128
#define DD 64
#define HH 512
#define VV 16000
#define GG 2048           // 4*H
#define BT (BB*TT)        // 8192
#define HS (HH*BB)        // one h/c state buffer: 512*64 = 32768 floats
#define NCTA 128          // persistent scan CTAs (co-resident on 148 SMs)

typedef unsigned long long ull;

// ---------------- f32x2 packed helpers ------------------------------------
__device__ __forceinline__ ull ffma2(ull a, ull b, ull c) {
    ull d; asm("fma.rn.f32x2 %0,%1,%2,%3;" : "=l"(d) : "l"(a), "l"(b), "l"(c)); return d;
}
__device__ __forceinline__ ull fadd2(ull a, ull b) {
    ull d; asm("add.rn.f32x2 %0,%1,%2;" : "=l"(d) : "l"(a), "l"(b)); return d;
}
__device__ __forceinline__ ull splat2(float x) {
    ull d; asm("mov.b64 %0,{%1,%1};" : "=l"(d) : "f"(x)); return d;
}
__device__ __forceinline__ float2 unpack2(ull v) {
    float2 r; asm("mov.b64 {%0,%1},%2;" : "=f"(r.x), "=f"(r.y) : "l"(v)); return r;
}

// ---------------- device scratch (allocation-free, static globals) --------
__device__ float g_x  [BT*DD];        // embeddings, row-major [r=b*T+t][D]
__device__ float g_xg [TT*GG*BB];     // gate pre-acts, t-major [t][4H][b]
__device__ float g_y  [BT*HH];        // layer output seq, row-major [r][H]
__device__ float g_h  [2*HS];         // h double buffer, transposed [k][b]
__device__ float g_c  [HS];           // c state, transposed [k][b]
__device__ float g_hf [2*HS];         // encoder final h per layer
__device__ float g_cf [2*HS];         // encoder final c per layer
__device__ unsigned g_bar;            // grid barrier arrive counter (stays 0 at rest)
__device__ unsigned g_gen;            // grid barrier generation

// ---------------- embedding gather ----------------------------------------
__global__ void gather_kernel(const int* __restrict__ batch,
                              const float* __restrict__ feat,
                              float* __restrict__ x)
{
    int r = blockIdx.x * 4 + (threadIdx.x >> 6);
    int d = threadIdx.x & 63;
    x[r * DD + d] = feat[batch[r] * DD + d];
}

// ---------------- SGEMM: C = A[M,K] * B[N,K]^T + bias1[n] + bias2[n] ------
// 128x128 tile, BK=16, 256 threads, 8x8 microtile via f32x2, double-buffered.
// scatter==0: C row-major [M,N].
// scatter==1: C[((m%T)*GG + n)*BB + m/T]  (t-major gate layout for the scan)
__global__ void __launch_bounds__(256) sgemm128(
    const float* __restrict__ A, const float* __restrict__ B,
    float* __restrict__ C,
    const float* __restrict__ bias1, const float* __restrict__ bias2,
    int M, int N, int K, int scatter)
{
    __shared__ float As[2][16][128];
    __shared__ float Bs[2][16][128];
    int tid = threadIdx.x;
    int m0 = blockIdx.y * 128;
    int n0 = blockIdx.x * 128;

    int lr = tid >> 2;            // 0..63
    int lc = (tid & 3) << 2;      // 0,4,8,12
    const float* Aload = A + (size_t)(m0 + lr) * K + lc;
    const float* Bload = B + (size_t)(n0 + lr) * K + lc;

    // preload k-tile 0
    float4 a0 = *(const float4*)(Aload);
    float4 a1 = *(const float4*)(Aload + (size_t)64 * K);
    float4 b0 = *(const float4*)(Bload);
    float4 b1 = *(const float4*)(Bload + (size_t)64 * K);
    As[0][lc+0][lr] = a0.x; As[0][lc+1][lr] = a0.y; As[0][lc+2][lr] = a0.z; As[0][lc+3][lr] = a0.w;
    As[0][lc+0][lr+64] = a1.x; As[0][lc+1][lr+64] = a1.y; As[0][lc+2][lr+64] = a1.z; As[0][lc+3][lr+64] = a1.w;
    Bs[0][lc+0][lr] = b0.x; Bs[0][lc+1][lr] = b0.y; Bs[0][lc+2][lr] = b0.z; Bs[0][lc+3][lr] = b0.w;
    Bs[0][lc+0][lr+64] = b1.x; Bs[0][lc+1][lr+64] = b1.y; Bs[0][lc+2][lr+64] = b1.z; Bs[0][lc+3][lr+64] = b1.w;
    __syncthreads();

    int tx = tid & 15, ty = tid >> 4;
    ull acc[8][4];
    #pragma unroll
    for (int i = 0; i < 8; i++)
        #pragma unroll
        for (int j = 0; j < 4; j++) acc[i][j] = 0ull;

    int nk = K >> 4;
    for (int kt = 0; kt < nk; kt++) {
        int cur = kt & 1;
        float4 na0, na1, nb0, nb1;
        bool has_next = (kt + 1 < nk);
        if (has_next) {
            const float* Ap = Aload + (kt + 1) * 16;
            const float* Bp = Bload + (kt + 1) * 16;
            na0 = *(const float4*)(Ap);
            na1 = *(const float4*)(Ap + (size_t)64 * K);
            nb0 = *(const float4*)(Bp);
            nb1 = *(const float4*)(Bp + (size_t)64 * K);
        }
        #pragma unroll
        for (int k = 0; k < 16; k++) {
            float a[8];
            *(float4*)(a)     = *(const float4*)&As[cur][k][ty * 8];
            *(float4*)(a + 4) = *(const float4*)&As[cur][k][ty * 8 + 4];
            ulonglong2 b01 = *(const ulonglong2*)&Bs[cur][k][tx * 8];
            ulonglong2 b23 = *(const ulonglong2*)&Bs[cur][k][tx * 8 + 4];
            #pragma unroll
            for (int i = 0; i < 8; i++) {
                ull ai = splat2(a[i]);
                acc[i][0] = ffma2(b01.x, ai, acc[i][0]);
                acc[i][1] = ffma2(b01.y, ai, acc[i][1]);
                acc[i][2] = ffma2(b23.x, ai, acc[i][2]);
                acc[i][3] = ffma2(b23.y, ai, acc[i][3]);
            }
        }
        if (has_next) {
            int nxt = cur ^ 1;
            As[nxt][lc+0][lr] = na0.x; As[nxt][lc+1][lr] = na0.y; As[nxt][lc+2][lr] = na0.z; As[nxt][lc+3][lr] = na0.w;
            As[nxt][lc+0][lr+64] = na1.x; As[nxt][lc+1][lr+64] = na1.y; As[nxt][lc+2][lr+64] = na1.z; As[nxt][lc+3][lr+64] = na1.w;
            Bs[nxt][lc+0][lr] = nb0.x; Bs[nxt][lc+1][lr] = nb0.y; Bs[nxt][lc+2][lr] = nb0.z; Bs[nxt][lc+3][lr] = nb0.w;
            Bs[nxt][lc+0][lr+64] = nb1.x; Bs[nxt][lc+1][lr+64] = nb1.y; Bs[nxt][lc+2][lr+64] = nb1.z; Bs[nxt][lc+3][lr+64] = nb1.w;
            __syncthreads();
        }
    }

    // epilogue
    float bcol[8];
    #pragma unroll
    for (int j = 0; j < 8; j++) {
        int n = n0 + tx * 8 + j;
        float bb = 0.f;
        if (bias1) bb += bias1[n];
        if (bias2) bb += bias2[n];
        bcol[j] = bb;
    }
    if (scatter == 0) {
        #pragma unroll
        for (int i = 0; i < 8; i++) {
            int m = m0 + ty * 8 + i;
            float* Crow = C + (size_t)m * N + n0 + tx * 8;
            float2 p0 = unpack2(acc[i][0]);
            float2 p1 = unpack2(acc[i][1]);
            float2 p2 = unpack2(acc[i][2]);
            float2 p3 = unpack2(acc[i][3]);
            float4 v0, v1;
            v0.x = p0.x + bcol[0]; v0.y = p0.y + bcol[1];
            v0.z = p1.x + bcol[2]; v0.w = p1.y + bcol[3];
            v1.x = p2.x + bcol[4]; v1.y = p2.y + bcol[5];
            v1.z = p3.x + bcol[6]; v1.w = p3.y + bcol[7];
            *(float4*)(Crow)     = v0;
            *(float4*)(Crow + 4) = v1;
        }
    } else {
        #pragma unroll
        for (int i = 0; i < 8; i++) {
            int m = m0 + ty * 8 + i;
            int t = m & (TT - 1);
            int b = m >> 7;          // T = 128
            float cv[8];
            float2 p0 = unpack2(acc[i][0]); cv[0] = p0.x; cv[1] = p0.y;
            float2 p1 = unpack2(acc[i][1]); cv[2] = p1.x; cv[3] = p1.y;
            float2 p2 = unpack2(acc[i][2]); cv[4] = p2.x; cv[5] = p2.y;
            float2 p3 = unpack2(acc[i][3]); cv[6] = p3.x; cv[7] = p3.y;
            #pragma unroll
            for (int j = 0; j < 8; j++) {
                int n = n0 + tx * 8 + j;
                C[((size_t)t * GG + n) * BB + b] = cv[j] + bcol[j];
            }
        }
    }
}

// ---------------- persistent LSTM layer kernel -----------------------------
// grid = 128 CTAs (co-resident), 256 threads. Each CTA owns 4 hidden units.
// Thread map: bp = tid&31 (b pair), d = (tid>>5)&3 (unit), ks = tid>>7 (K half).
// Whh resident in smem for all 128 steps; c held in registers (ks==0 threads).
// Grid-wide barrier per step: atom.release arrive + ld.acquire generation poll.
__global__ void __launch_bounds__(256) lstm_layer(
    const float* __restrict__ xg, const float* __restrict__ Whh,
    float* __restrict__ h, float* __restrict__ c, float* __restrict__ y)
{
    __shared__ float ws[512 * 16];        // ws[k][d*4+g], 32 KB
    __shared__ ull   red[128 * 4];        // ks=1 partials, 4 KB

    int tid = threadIdx.x;
    int jj0 = blockIdx.x << 2;

    // load the 16 needed Whh rows, transposed into ws[k][d*4+g]
    for (int i = tid; i < 16 * 512; i += 256) {
        int r = i >> 9;                   // 0..15
        int k = i & 511;
        int dd = r & 3, g = r >> 2;
        ws[k * 16 + dd * 4 + g] = Whh[((size_t)g * HH + jj0 + dd) * HH + k];
    }

    int bp = tid & 31;
    int d  = (tid >> 5) & 3;
    int ks = tid >> 7;
    int jj = jj0 + d;

    unsigned mygen = *(volatile unsigned*)&g_gen;   // stable until first barrier

    float2 c2 = make_float2(0.f, 0.f);
    if (ks == 0) c2 = *(const float2*)&c[jj * BB + 2 * bp];
    __syncthreads();

    for (int t = 0; t < TT; t++) {
        const float* h_prev = h + (t & 1) * HS;
        float*       h_next = h + ((t + 1) & 1) * HS;

        // prefetch xg gate pre-activations (overlaps the dot product)
        float2 xi2, xf2, xgg2, xo2;
        if (ks == 0) {
            const float* p = xg + (size_t)t * GG * BB + 2 * bp;
            xi2  = *(const float2*)(p + (size_t)(jj         ) * BB);
            xf2  = *(const float2*)(p + (size_t)(jj + HH    ) * BB);
            xgg2 = *(const float2*)(p + (size_t)(jj + 2 * HH) * BB);
            xo2  = *(const float2*)(p + (size_t)(jj + 3 * HH) * BB);
        }

        // dot product over this thread's K half (256 k) for 4 gates x 2 b
        const float2* hp = (const float2*)h_prev + (size_t)ks * 256 * 32 + bp;
        ull a01b0 = 0ull, a23b0 = 0ull, a01b1 = 0ull, a23b1 = 0ull;

        float2 hreg[16];
        #pragma unroll
        for (int u = 0; u < 16; u++) hreg[u] = hp[u * 32];

        for (int kb = 0; kb < 16; kb++) {
            float2 hn[16];
            if (kb < 15) {
                #pragma unroll
                for (int u = 0; u < 16; u++) hn[u] = hp[((kb + 1) * 16 + u) * 32];
            }
            #pragma unroll
            for (int u = 0; u < 16; u++) {
                int k = (ks << 8) + (kb << 4) + u;
                ulonglong2 w = *(const ulonglong2*)&ws[k * 16 + d * 4];
                ull hb0 = splat2(hreg[u].x);
                ull hb1 = splat2(hreg[u].y);
                a01b0 = ffma2(w.x, hb0, a01b0);
                a23b0 = ffma2(w.y, hb0, a23b0);
                a01b1 = ffma2(w.x, hb1, a01b1);
                a23b1 = ffma2(w.y, hb1, a23b1);
            }
            #pragma unroll
            for (int u = 0; u < 16; u++) hreg[u] = hn[u];
        }

        // cross-ks reduction
        if (ks == 1) {
            ull* r = &red[(tid & 127) * 4];
            r[0] = a01b0; r[1] = a23b0; r[2] = a01b1; r[3] = a23b1;
        }
        __syncthreads();
        if (ks == 0) {
            ull* r = &red[tid * 4];
            a01b0 = fadd2(a01b0, r[0]);
            a23b0 = fadd2(a23b0, r[1]);
            a01b1 = fadd2(a01b1, r[2]);
            a23b1 = fadd2(a23b1, r[3]);

            float2 if0 = unpack2(a01b0);   // (i, f) for b0
            float2 go0 = unpack2(a23b0);   // (g, o) for b0
            float2 if1 = unpack2(a01b1);
            float2 go1 = unpack2(a23b1);

            float gi0 = 1.f / (1.f + expf(-(if0.x + xi2.x)));
            float gf0 = 1.f / (1.f + expf(-(if0.y + xf2.x)));
            float gg0 = tanhf(go0.x + xgg2.x);
            float go_0 = 1.f / (1.f + expf(-(go0.y + xo2.x)));
            float gi1 = 1.f / (1.f + expf(-(if1.x + xi2.y)));
            float gf1 = 1.f / (1.f + expf(-(if1.y + xf2.y)));
            float gg1 = tanhf(go1.x + xgg2.y);
            float go_1 = 1.f / (1.f + expf(-(go1.y + xo2.y)));

            c2.x = gf0 * c2.x + gi0 * gg0;
            c2.y = gf1 * c2.y + gi1 * gg1;
            float hv0 = go_0 * tanhf(c2.x);
            float hv1 = go_1 * tanhf(c2.y);

            *(float2*)&h_next[jj * BB + 2 * bp] = make_float2(hv0, hv1);
            y[((size_t)(2 * bp    ) * TT + t) * HH + jj] = hv0;
            y[((size_t)(2 * bp + 1) * TT + t) * HH + jj] = hv1;
        }
        __syncthreads();

        // grid-wide barrier (release h_next, acquire everyone else's)
        if (tid == 0) {
            unsigned* barp = &g_bar;
            unsigned* genp = &g_gen;
            unsigned old;
            asm volatile("atom.release.gpu.global.add.u32 %0, [%1], %2;"
                         : "=r"(old) : "l"(barp), "r"(1u) : "memory");
            if (old == NCTA - 1) {
                asm volatile("st.relaxed.gpu.global.u32 [%0], %1;"
                             :: "l"(barp), "r"(0u) : "memory");
                asm volatile("red.release.gpu.global.add.u32 [%0], %1;"
                             :: "l"(genp), "r"(1u) : "memory");
            } else {
                unsigned cur;
                do {
                    asm volatile("ld.acquire.gpu.global.u32 %0, [%1];"
                                 : "=r"(cur) : "l"(genp) : "memory");
                } while (cur == mygen);
            }
            mygen++;
        }
        __syncthreads();
    }

    if (ks == 0) *(float2*)&c[jj * BB + 2 * bp] = c2;
}

// ---------------- row softmax (in-place, row buffered in dyn smem) --------
__global__ void __launch_bounds__(256) softmax_kernel(float* __restrict__ P, int N)
{
    extern __shared__ float row[];
    __shared__ float red[8];
    int tid = threadIdx.x;
    float* p = P + (size_t)blockIdx.x * N;

    float mx = -3.4e38f;
    for (int i = tid * 4; i < N; i += 1024) {
        float4 v = *(const float4*)(p + i);
        *(float4*)(row + i) = v;
        mx = fmaxf(mx, fmaxf(fmaxf(v.x, v.y), fmaxf(v.z, v.w)));
    }
    #pragma unroll
    for (int o = 16; o; o >>= 1) mx = fmaxf(mx, __shfl_xor_sync(0xffffffffu, mx, o));
    if ((tid & 31) == 0) red[tid >> 5] = mx;
    __syncthreads();
    float m = red[0];
    #pragma unroll
    for (int w = 1; w < 8; w++) m = fmaxf(m, red[w]);
    __syncthreads();

    float sum = 0.f;
    for (int i = tid * 4; i < N; i += 1024) {
        float4 v = *(float4*)(row + i);
        v.x = expf(v.x - m); v.y = expf(v.y - m);
        v.z = expf(v.z - m); v.w = expf(v.w - m);
        sum += (v.x + v.y) + (v.z + v.w);
        *(float4*)(row + i) = v;
    }
    #pragma unroll
    for (int o = 16; o; o >>= 1) sum += __shfl_xor_sync(0xffffffffu, sum, o);
    if ((tid & 31) == 0) red[tid >> 5] = sum;
    __syncthreads();
    float tot = 0.f;
    #pragma unroll
    for (int w = 0; w < 8; w++) tot += red[w];
    float inv = 1.f / tot;

    for (int i = tid * 4; i < N; i += 1024) {
        float4 v = *(float4*)(row + i);
        v.x *= inv; v.y *= inv; v.z *= inv; v.w *= inv;
        *(float4*)(p + i) = v;
    }
}

// ---------------- host orchestration --------------------------------------
extern "C" void kernel_launch(void* const* d_in, const int* in_sizes, int n_in,
                              void* d_out, int out_size)
{
    const int*   batch    = (const int*)d_in[0];
    const float* features = (const float*)d_in[1];
    const float* eWih0 = (const float*)d_in[2];
    const float* eWhh0 = (const float*)d_in[3];
    const float* ebih0 = (const float*)d_in[4];
    const float* ebhh0 = (const float*)d_in[5];
    const float* eWih1 = (const float*)d_in[6];
    const float* eWhh1 = (const float*)d_in[7];
    const float* ebih1 = (const float*)d_in[8];
    const float* ebhh1 = (const float*)d_in[9];
    const float* dWih0 = (const float*)d_in[10];
    const float* dWhh0 = (const float*)d_in[11];
    const float* dbih0 = (const float*)d_in[12];
    const float* dbhh0 = (const float*)d_in[13];
    const float* dWih1 = (const float*)d_in[14];
    const float* dWhh1 = (const float*)d_in[15];
    const float* dbih1 = (const float*)d_in[16];
    const float* dbhh1 = (const float*)d_in[17];
    const float* linW  = (const float*)d_in[18];
    const float* linb  = (const float*)d_in[19];
    float* out = (float*)d_out;

    float *gx, *gxg, *gy, *gh, *gc, *ghf, *gcf;
    cudaGetSymbolAddress((void**)&gx,  g_x);
    cudaGetSymbolAddress((void**)&gxg, g_xg);
    cudaGetSymbolAddress((void**)&gy,  g_y);
    cudaGetSymbolAddress((void**)&gh,  g_h);
    cudaGetSymbolAddress((void**)&gc,  g_c);
    cudaGetSymbolAddress((void**)&ghf, g_hf);
    cudaGetSymbolAddress((void**)&gcf, g_cf);

    cudaFuncSetAttribute(softmax_kernel,
                         cudaFuncAttributeMaxDynamicSharedMemorySize, VV * 4);

    // 1) embedding gather
    gather_kernel<<<BT / 4, 256>>>(batch, features, gx);

    dim3 gridG(GG / 128, BT / 128);     // xg GEMMs: [8192 x 2048]
    dim3 gridL(VV / 128, BT / 128);     // logits GEMM: [8192 x 16000]

    // ---- encoder layer 0 ----
    sgemm128<<<gridG, 256>>>(gx, eWih0, gxg, ebih0, ebhh0, BT, GG, DD, 1);
    cudaMemsetAsync(gh, 0, HS * sizeof(float), 0);
    cudaMemsetAsync(gc, 0, HS * sizeof(float), 0);
    lstm_layer<<<NCTA, 256>>>(gxg, eWhh0, gh, gc, gy);
    cudaMemcpyAsync(ghf,      gh, HS * sizeof(float), cudaMemcpyDeviceToDevice, 0);
    cudaMemcpyAsync(gcf,      gc, HS * sizeof(float), cudaMemcpyDeviceToDevice, 0);

    // ---- encoder layer 1 ----
    sgemm128<<<gridG, 256>>>(gy, eWih1, gxg, ebih1, ebhh1, BT, GG, HH, 1);
    cudaMemsetAsync(gh, 0, HS * sizeof(float), 0);
    cudaMemsetAsync(gc, 0, HS * sizeof(float), 0);
    lstm_layer<<<NCTA, 256>>>(gxg, eWhh1, gh, gc, gy);
    cudaMemcpyAsync(ghf + HS, gh, HS * sizeof(float), cudaMemcpyDeviceToDevice, 0);
    cudaMemcpyAsync(gcf + HS, gc, HS * sizeof(float), cudaMemcpyDeviceToDevice, 0);

    // ---- decoder layer 0 (init from encoder layer-0 finals) ----
    sgemm128<<<gridG, 256>>>(gx, dWih0, gxg, dbih0, dbhh0, BT, GG, DD, 1);
    cudaMemcpyAsync(gh, ghf,      HS * sizeof(float), cudaMemcpyDeviceToDevice, 0);
    cudaMemcpyAsync(gc, gcf,      HS * sizeof(float), cudaMemcpyDeviceToDevice, 0);
    lstm_layer<<<NCTA, 256>>>(gxg, dWhh0, gh, gc, gy);

    // ---- decoder layer 1 (init from encoder layer-1 finals) ----
    sgemm128<<<gridG, 256>>>(gy, dWih1, gxg, dbih1, dbhh1, BT, GG, HH, 1);
    cudaMemcpyAsync(gh, ghf + HS, HS * sizeof(float), cudaMemcpyDeviceToDevice, 0);
    cudaMemcpyAsync(gc, gcf + HS, HS * sizeof(float), cudaMemcpyDeviceToDevice, 0);
    lstm_layer<<<NCTA, 256>>>(gxg, dWhh1, gh, gc, gy);

    // ---- logits + softmax ----
    sgemm128<<<gridL, 256>>>(gy, linW, out, linb, (const float*)0, BT, VV, HH, 0);
    softmax_kernel<<<BT, 256, VV * 4>>>(out, VV);

    (void)in_sizes; (void)n_in; (void)out_size;
}

// round 9
// speedup vs baseline: 1.7419x; 1.5615x over previous
#include <cuda_runtime.h>
#include <cuda_bf16.h>
#include <math.h>

#define BB 64
#define TT 128
#define DD 64
#define HH 512
#define VV 16000
#define GG 2048           // 4*H
#define BT (BB*TT)        // 8192
#define HS (HH*BB)        // one h/c state buffer: 512*64 = 32768 floats
#define NCTA 128          // persistent scan CTAs (co-resident on 148 SMs)

typedef unsigned long long ull;

// ---------------- f32x2 packed helpers (scan kernel) -----------------------
__device__ __forceinline__ ull ffma2(ull a, ull b, ull c) {
    ull d; asm("fma.rn.f32x2 %0,%1,%2,%3;" : "=l"(d) : "l"(a), "l"(b), "l"(c)); return d;
}
__device__ __forceinline__ ull fadd2(ull a, ull b) {
    ull d; asm("add.rn.f32x2 %0,%1,%2;" : "=l"(d) : "l"(a), "l"(b)); return d;
}
__device__ __forceinline__ ull splat2(float x) {
    ull d; asm("mov.b64 %0,{%1,%1};" : "=l"(d) : "f"(x)); return d;
}
__device__ __forceinline__ float2 unpack2(ull v) {
    float2 r; asm("mov.b64 {%0,%1},%2;" : "=f"(r.x), "=f"(r.y) : "l"(v)); return r;
}

// ---------------- tensor-core helpers --------------------------------------
__device__ __forceinline__ void ldsm4(unsigned* r, unsigned addr) {
    asm volatile("ldmatrix.sync.aligned.m8n8.x4.shared.b16 {%0,%1,%2,%3},[%4];"
                 : "=r"(r[0]), "=r"(r[1]), "=r"(r[2]), "=r"(r[3]) : "r"(addr));
}
__device__ __forceinline__ void mma_bf16(float* d, const unsigned* a,
                                         unsigned b0, unsigned b1) {
    asm volatile("mma.sync.aligned.m16n8k16.row.col.f32.bf16.bf16.f32 "
                 "{%0,%1,%2,%3},{%4,%5,%6,%7},{%8,%9},{%0,%1,%2,%3};"
                 : "+f"(d[0]), "+f"(d[1]), "+f"(d[2]), "+f"(d[3])
                 : "r"(a[0]), "r"(a[1]), "r"(a[2]), "r"(a[3]), "r"(b0), "r"(b1));
}

// ---------------- device scratch (allocation-free, static globals) --------
__device__ float g_xg [TT*GG*BB];              // gate pre-acts, t-major [t][4H][b]
__device__ float g_y  [BT*HH];                 // layer output seq [b*T+t][H]
__device__ float g_h  [2*HS];                  // h double buffer, transposed [k][b]
__device__ float g_c  [HS];                    // c state, transposed [k][b]
__device__ float g_hf [2*HS];                  // encoder final h per layer
__device__ float g_cf [2*HS];                  // encoder final c per layer
__device__ unsigned g_bar;                     // grid barrier arrive counter
__device__ unsigned g_gen;                     // grid barrier generation
__device__ __nv_bfloat16 g_Ax [BT*192];        // split embeddings [8192][3*64]
__device__ __nv_bfloat16 g_Aab[BT*1536];       // split activations [8192][3*512]
__device__ __nv_bfloat16 g_Bbf[VV*1536];       // split weights (reused per GEMM)

// ---------------- embedding gather + split (A'-mode: hi,lo,hi) -------------
__global__ void gather_split(const int* __restrict__ batch,
                             const float* __restrict__ feat,
                             __nv_bfloat16* __restrict__ dst)
{
    int idx = blockIdx.x * 256 + threadIdx.x;   // over BT*DD
    int r = idx >> 6, k = idx & 63;
    float x = feat[batch[r] * DD + k];
    __nv_bfloat16 hi = __float2bfloat16_rn(x);
    __nv_bfloat16 lo = __float2bfloat16_rn(x - __bfloat162float(hi));
    size_t base = (size_t)r * 192;
    dst[base + k]       = hi;
    dst[base + 64 + k]  = lo;
    dst[base + 128 + k] = hi;
}

// ---------------- fp32 -> split-bf16: mode0 A'=[hi,lo,hi], mode1 B'=[hi,hi,lo]
__global__ void split_kernel(const float* __restrict__ src,
                             __nv_bfloat16* __restrict__ dst, int K, int mode)
{
    int idx = blockIdx.x * 256 + threadIdx.x;   // over M*K
    int m = idx / K, k = idx - m * K;
    float x = src[idx];
    __nv_bfloat16 hi = __float2bfloat16_rn(x);
    __nv_bfloat16 lo = __float2bfloat16_rn(x - __bfloat162float(hi));
    size_t base = (size_t)m * 3 * K;
    dst[base + k] = hi;
    if (mode == 0) { dst[base + K + k] = lo; dst[base + 2 * K + k] = hi; }
    else           { dst[base + K + k] = hi; dst[base + 2 * K + k] = lo; }
}

// ---------------- bf16 tensor-core GEMM ------------------------------------
// C[M,N] = A'[M,Kp] * B'[N,Kp]^T + bias1[n] + bias2[n]
// Tile 128x128, BK=32, 256 threads = 8 warps (2m x 4n), warp tile 64x32.
// smem XOR-swizzled 16B chunks: chunk' = chunk ^ ((row>>1)&3).
// scatter==0: C row-major; scatter==1: C[((m%T)*GG + n)*BB + m/T].
__global__ void __launch_bounds__(256) hgemm(
    const __nv_bfloat16* __restrict__ A, const __nv_bfloat16* __restrict__ B,
    float* __restrict__ C,
    const float* __restrict__ bias1, const float* __restrict__ bias2,
    int Kp, int N, int scatter)
{
    __shared__ __align__(16) __nv_bfloat16 sA[2][128 * 32];
    __shared__ __align__(16) __nv_bfloat16 sB[2][128 * 32];

    int tid = threadIdx.x;
    int m0 = blockIdx.y * 128, n0 = blockIdx.x * 128;
    int lane = tid & 31, warp = tid >> 5;
    int wm = warp >> 2, wn = warp & 3;

    // loader: threads 0..127 load one A row (64 B), 128..255 one B row
    int lrow = tid & 127;
    const __nv_bfloat16* src = (tid < 128)
        ? A + (size_t)(m0 + lrow) * Kp
        : B + (size_t)(n0 + lrow) * Kp;
    int swz = (lrow >> 1) & 3;

    float acc[4][4][4];
    #pragma unroll
    for (int i = 0; i < 4; i++)
        #pragma unroll
        for (int j = 0; j < 4; j++)
            #pragma unroll
            for (int r = 0; r < 4; r++) acc[i][j][r] = 0.f;

    // preload k-tile 0
    {
        const uint4* s = (const uint4*)src;
        __nv_bfloat16* drow = ((tid < 128) ? sA[0] : sB[0]) + lrow * 32;
        #pragma unroll
        for (int c = 0; c < 4; c++) ((uint4*)drow)[c ^ swz] = s[c];
    }
    __syncthreads();

    int nk = Kp >> 5;
    for (int kt = 0; kt < nk; kt++) {
        int cur = kt & 1;
        bool hn = (kt + 1 < nk);
        uint4 v[4];
        if (hn) {
            const uint4* s = (const uint4*)(src + (kt + 1) * 32);
            #pragma unroll
            for (int c = 0; c < 4; c++) v[c] = s[c];
        }
        unsigned sa = (unsigned)__cvta_generic_to_shared(sA[cur]);
        unsigned sb = (unsigned)__cvta_generic_to_shared(sB[cur]);

        #pragma unroll
        for (int kk = 0; kk < 2; kk++) {
            unsigned afr[4][4];
            #pragma unroll
            for (int mb = 0; mb < 4; mb++) {
                int row = wm * 64 + mb * 16 + (lane & 15);
                int c = (kk * 2 + (lane >> 4)) ^ ((row >> 1) & 3);
                ldsm4(afr[mb], sa + row * 64 + c * 16);
            }
            unsigned bfr[2][4];
            #pragma unroll
            for (int nb2 = 0; nb2 < 2; nb2++) {
                int row = wn * 32 + nb2 * 16 + (lane & 7) + ((lane >> 4) << 3);
                int c = (kk * 2 + ((lane >> 3) & 1)) ^ ((row >> 1) & 3);
                ldsm4(bfr[nb2], sb + row * 64 + c * 16);
            }
            #pragma unroll
            for (int mb = 0; mb < 4; mb++)
                #pragma unroll
                for (int nb = 0; nb < 4; nb++) {
                    const unsigned* bp = &bfr[nb >> 1][(nb & 1) * 2];
                    mma_bf16(acc[mb][nb], afr[mb], bp[0], bp[1]);
                }
        }
        if (hn) {
            int nxt = cur ^ 1;
            __nv_bfloat16* drow = ((tid < 128) ? sA[nxt] : sB[nxt]) + lrow * 32;
            #pragma unroll
            for (int c = 0; c < 4; c++) ((uint4*)drow)[c ^ swz] = v[c];
            __syncthreads();
        }
    }

    // epilogue
    #pragma unroll
    for (int nb = 0; nb < 4; nb++) {
        int col = n0 + wn * 32 + nb * 8 + (lane & 3) * 2;
        float b0 = 0.f, b1 = 0.f;
        if (bias1) { b0 += bias1[col]; b1 += bias1[col + 1]; }
        if (bias2) { b0 += bias2[col]; b1 += bias2[col + 1]; }
        #pragma unroll
        for (int mb = 0; mb < 4; mb++) {
            int row = m0 + wm * 64 + mb * 16 + (lane >> 2);
            float* d = acc[mb][nb];
            if (scatter == 0) {
                *(float2*)(C + (size_t)row * N + col) =
                    make_float2(d[0] + b0, d[1] + b1);
                *(float2*)(C + (size_t)(row + 8) * N + col) =
                    make_float2(d[2] + b0, d[3] + b1);
            } else {
                int t0 = row & (TT - 1), bb0i = row >> 7;
                int r2 = row + 8;
                int t1 = r2 & (TT - 1), bb1i = r2 >> 7;
                C[((size_t)t0 * GG + col    ) * BB + bb0i] = d[0] + b0;
                C[((size_t)t0 * GG + col + 1) * BB + bb0i] = d[1] + b1;
                C[((size_t)t1 * GG + col    ) * BB + bb1i] = d[2] + b0;
                C[((size_t)t1 * GG + col + 1) * BB + bb1i] = d[3] + b1;
            }
        }
    }
}

// ---------------- persistent LSTM layer kernel (unchanged, fp32) -----------
__global__ void __launch_bounds__(256) lstm_layer(
    const float* __restrict__ xg, const float* __restrict__ Whh,
    float* __restrict__ h, float* __restrict__ c, float* __restrict__ y)
{
    __shared__ float ws[512 * 16];        // ws[k][d*4+g], 32 KB
    __shared__ ull   red[128 * 4];        // ks=1 partials, 4 KB

    int tid = threadIdx.x;
    int jj0 = blockIdx.x << 2;

    for (int i = tid; i < 16 * 512; i += 256) {
        int r = i >> 9;
        int k = i & 511;
        int dd = r & 3, g = r >> 2;
        ws[k * 16 + dd * 4 + g] = Whh[((size_t)g * HH + jj0 + dd) * HH + k];
    }

    int bp = tid & 31;
    int d  = (tid >> 5) & 3;
    int ks = tid >> 7;
    int jj = jj0 + d;

    unsigned mygen = *(volatile unsigned*)&g_gen;

    float2 c2 = make_float2(0.f, 0.f);
    if (ks == 0) c2 = *(const float2*)&c[jj * BB + 2 * bp];
    __syncthreads();

    for (int t = 0; t < TT; t++) {
        const float* h_prev = h + (t & 1) * HS;
        float*       h_next = h + ((t + 1) & 1) * HS;

        float2 xi2, xf2, xgg2, xo2;
        if (ks == 0) {
            const float* p = xg + (size_t)t * GG * BB + 2 * bp;
            xi2  = *(const float2*)(p + (size_t)(jj         ) * BB);
            xf2  = *(const float2*)(p + (size_t)(jj + HH    ) * BB);
            xgg2 = *(const float2*)(p + (size_t)(jj + 2 * HH) * BB);
            xo2  = *(const float2*)(p + (size_t)(jj + 3 * HH) * BB);
        }

        const float2* hp = (const float2*)h_prev + (size_t)ks * 256 * 32 + bp;
        ull a01b0 = 0ull, a23b0 = 0ull, a01b1 = 0ull, a23b1 = 0ull;

        float2 hreg[16];
        #pragma unroll
        for (int u = 0; u < 16; u++) hreg[u] = hp[u * 32];

        for (int kb = 0; kb < 16; kb++) {
            float2 hn[16];
            if (kb < 15) {
                #pragma unroll
                for (int u = 0; u < 16; u++) hn[u] = hp[((kb + 1) * 16 + u) * 32];
            }
            #pragma unroll
            for (int u = 0; u < 16; u++) {
                int k = (ks << 8) + (kb << 4) + u;
                ulonglong2 w = *(const ulonglong2*)&ws[k * 16 + d * 4];
                ull hb0 = splat2(hreg[u].x);
                ull hb1 = splat2(hreg[u].y);
                a01b0 = ffma2(w.x, hb0, a01b0);
                a23b0 = ffma2(w.y, hb0, a23b0);
                a01b1 = ffma2(w.x, hb1, a01b1);
                a23b1 = ffma2(w.y, hb1, a23b1);
            }
            #pragma unroll
            for (int u = 0; u < 16; u++) hreg[u] = hn[u];
        }

        if (ks == 1) {
            ull* r = &red[(tid & 127) * 4];
            r[0] = a01b0; r[1] = a23b0; r[2] = a01b1; r[3] = a23b1;
        }
        __syncthreads();
        if (ks == 0) {
            ull* r = &red[tid * 4];
            a01b0 = fadd2(a01b0, r[0]);
            a23b0 = fadd2(a23b0, r[1]);
            a01b1 = fadd2(a01b1, r[2]);
            a23b1 = fadd2(a23b1, r[3]);

            float2 if0 = unpack2(a01b0);
            float2 go0 = unpack2(a23b0);
            float2 if1 = unpack2(a01b1);
            float2 go1 = unpack2(a23b1);

            float gi0 = 1.f / (1.f + expf(-(if0.x + xi2.x)));
            float gf0 = 1.f / (1.f + expf(-(if0.y + xf2.x)));
            float gg0 = tanhf(go0.x + xgg2.x);
            float go_0 = 1.f / (1.f + expf(-(go0.y + xo2.x)));
            float gi1 = 1.f / (1.f + expf(-(if1.x + xi2.y)));
            float gf1 = 1.f / (1.f + expf(-(if1.y + xf2.y)));
            float gg1 = tanhf(go1.x + xgg2.y);
            float go_1 = 1.f / (1.f + expf(-(go1.y + xo2.y)));

            c2.x = gf0 * c2.x + gi0 * gg0;
            c2.y = gf1 * c2.y + gi1 * gg1;
            float hv0 = go_0 * tanhf(c2.x);
            float hv1 = go_1 * tanhf(c2.y);

            *(float2*)&h_next[jj * BB + 2 * bp] = make_float2(hv0, hv1);
            y[((size_t)(2 * bp    ) * TT + t) * HH + jj] = hv0;
            y[((size_t)(2 * bp + 1) * TT + t) * HH + jj] = hv1;
        }
        __syncthreads();

        if (tid == 0) {
            unsigned* barp = &g_bar;
            unsigned* genp = &g_gen;
            unsigned old;
            asm volatile("atom.release.gpu.global.add.u32 %0, [%1], %2;"
                         : "=r"(old) : "l"(barp), "r"(1u) : "memory");
            if (old == NCTA - 1) {
                asm volatile("st.relaxed.gpu.global.u32 [%0], %1;"
                             :: "l"(barp), "r"(0u) : "memory");
                asm volatile("red.release.gpu.global.add.u32 [%0], %1;"
                             :: "l"(genp), "r"(1u) : "memory");
            } else {
                unsigned cur;
                do {
                    asm volatile("ld.acquire.gpu.global.u32 %0, [%1];"
                                 : "=r"(cur) : "l"(genp) : "memory");
                } while (cur == mygen);
            }
            mygen++;
        }
        __syncthreads();
    }

    if (ks == 0) *(float2*)&c[jj * BB + 2 * bp] = c2;
}

// ---------------- row softmax (in-place, row buffered in dyn smem) --------
__global__ void __launch_bounds__(256) softmax_kernel(float* __restrict__ P, int N)
{
    extern __shared__ float row[];
    __shared__ float red[8];
    int tid = threadIdx.x;
    float* p = P + (size_t)blockIdx.x * N;

    float mx = -3.4e38f;
    for (int i = tid * 4; i < N; i += 1024) {
        float4 v = *(const float4*)(p + i);
        *(float4*)(row + i) = v;
        mx = fmaxf(mx, fmaxf(fmaxf(v.x, v.y), fmaxf(v.z, v.w)));
    }
    #pragma unroll
    for (int o = 16; o; o >>= 1) mx = fmaxf(mx, __shfl_xor_sync(0xffffffffu, mx, o));
    if ((tid & 31) == 0) red[tid >> 5] = mx;
    __syncthreads();
    float m = red[0];
    #pragma unroll
    for (int w = 1; w < 8; w++) m = fmaxf(m, red[w]);
    __syncthreads();

    float sum = 0.f;
    for (int i = tid * 4; i < N; i += 1024) {
        float4 v = *(float4*)(row + i);
        v.x = expf(v.x - m); v.y = expf(v.y - m);
        v.z = expf(v.z - m); v.w = expf(v.w - m);
        sum += (v.x + v.y) + (v.z + v.w);
        *(float4*)(row + i) = v;
    }
    #pragma unroll
    for (int o = 16; o; o >>= 1) sum += __shfl_xor_sync(0xffffffffu, sum, o);
    if ((tid & 31) == 0) red[tid >> 5] = sum;
    __syncthreads();
    float tot = 0.f;
    #pragma unroll
    for (int w = 0; w < 8; w++) tot += red[w];
    float inv = 1.f / tot;

    for (int i = tid * 4; i < N; i += 1024) {
        float4 v = *(float4*)(row + i);
        v.x *= inv; v.y *= inv; v.z *= inv; v.w *= inv;
        *(float4*)(p + i) = v;
    }
}

// ---------------- host orchestration --------------------------------------
extern "C" void kernel_launch(void* const* d_in, const int* in_sizes, int n_in,
                              void* d_out, int out_size)
{
    const int*   batch    = (const int*)d_in[0];
    const float* features = (const float*)d_in[1];
    const float* eWih0 = (const float*)d_in[2];
    const float* eWhh0 = (const float*)d_in[3];
    const float* ebih0 = (const float*)d_in[4];
    const float* ebhh0 = (const float*)d_in[5];
    const float* eWih1 = (const float*)d_in[6];
    const float* eWhh1 = (const float*)d_in[7];
    const float* ebih1 = (const float*)d_in[8];
    const float* ebhh1 = (const float*)d_in[9];
    const float* dWih0 = (const float*)d_in[10];
    const float* dWhh0 = (const float*)d_in[11];
    const float* dbih0 = (const float*)d_in[12];
    const float* dbhh0 = (const float*)d_in[13];
    const float* dWih1 = (const float*)d_in[14];
    const float* dWhh1 = (const float*)d_in[15];
    const float* dbih1 = (const float*)d_in[16];
    const float* dbhh1 = (const float*)d_in[17];
    const float* linW  = (const float*)d_in[18];
    const float* linb  = (const float*)d_in[19];
    float* out = (float*)d_out;

    float *gxg, *gy, *gh, *gc, *ghf, *gcf;
    __nv_bfloat16 *gAx, *gAab, *gBbf;
    cudaGetSymbolAddress((void**)&gxg, g_xg);
    cudaGetSymbolAddress((void**)&gy,  g_y);
    cudaGetSymbolAddress((void**)&gh,  g_h);
    cudaGetSymbolAddress((void**)&gc,  g_c);
    cudaGetSymbolAddress((void**)&ghf, g_hf);
    cudaGetSymbolAddress((void**)&gcf, g_cf);
    cudaGetSymbolAddress((void**)&gAx,  g_Ax);
    cudaGetSymbolAddress((void**)&gAab, g_Aab);
    cudaGetSymbolAddress((void**)&gBbf, g_Bbf);

    cudaFuncSetAttribute(softmax_kernel,
                         cudaFuncAttributeMaxDynamicSharedMemorySize, VV * 4);

    dim3 gridG(GG / 128, BT / 128);     // xg GEMMs: [8192 x 2048]
    dim3 gridL(VV / 128, BT / 128);     // logits GEMM: [8192 x 16000]

    // embedding gather + split (used by enc0 and dec0)
    gather_split<<<(BT * DD) / 256, 256>>>(batch, features, gAx);

    // ---- encoder layer 0 ----
    split_kernel<<<(GG * DD) / 256, 256>>>(eWih0, gBbf, DD, 1);
    hgemm<<<gridG, 256>>>(gAx, gBbf, gxg, ebih0, ebhh0, 3 * DD, GG, 1);
    cudaMemsetAsync(gh, 0, HS * sizeof(float), 0);
    cudaMemsetAsync(gc, 0, HS * sizeof(float), 0);
    lstm_layer<<<NCTA, 256>>>(gxg, eWhh0, gh, gc, gy);
    cudaMemcpyAsync(ghf,      gh, HS * sizeof(float), cudaMemcpyDeviceToDevice, 0);
    cudaMemcpyAsync(gcf,      gc, HS * sizeof(float), cudaMemcpyDeviceToDevice, 0);

    // ---- encoder layer 1 ----
    split_kernel<<<(BT * HH) / 256, 256>>>(gy, gAab, HH, 0);
    split_kernel<<<(GG * HH) / 256, 256>>>(eWih1, gBbf, HH, 1);
    hgemm<<<gridG, 256>>>(gAab, gBbf, gxg, ebih1, ebhh1, 3 * HH, GG, 1);
    cudaMemsetAsync(gh, 0, HS * sizeof(float), 0);
    cudaMemsetAsync(gc, 0, HS * sizeof(float), 0);
    lstm_layer<<<NCTA, 256>>>(gxg, eWhh1, gh, gc, gy);
    cudaMemcpyAsync(ghf + HS, gh, HS * sizeof(float), cudaMemcpyDeviceToDevice, 0);
    cudaMemcpyAsync(gcf + HS, gc, HS * sizeof(float), cudaMemcpyDeviceToDevice, 0);

    // ---- decoder layer 0 (init from encoder layer-0 finals) ----
    split_kernel<<<(GG * DD) / 256, 256>>>(dWih0, gBbf, DD, 1);
    hgemm<<<gridG, 256>>>(gAx, gBbf, gxg, dbih0, dbhh0, 3 * DD, GG, 1);
    cudaMemcpyAsync(gh, ghf,      HS * sizeof(float), cudaMemcpyDeviceToDevice, 0);
    cudaMemcpyAsync(gc, gcf,      HS * sizeof(float), cudaMemcpyDeviceToDevice, 0);
    lstm_layer<<<NCTA, 256>>>(gxg, dWhh0, gh, gc, gy);

    // ---- decoder layer 1 (init from encoder layer-1 finals) ----
    split_kernel<<<(BT * HH) / 256, 256>>>(gy, gAab, HH, 0);
    split_kernel<<<(GG * HH) / 256, 256>>>(dWih1, gBbf, HH, 1);
    hgemm<<<gridG, 256>>>(gAab, gBbf, gxg, dbih1, dbhh1, 3 * HH, GG, 1);
    cudaMemcpyAsync(gh, ghf + HS, HS * sizeof(float), cudaMemcpyDeviceToDevice, 0);
    cudaMemcpyAsync(gc, gcf + HS, HS * sizeof(float), cudaMemcpyDeviceToDevice, 0);
    lstm_layer<<<NCTA, 256>>>(gxg, dWhh1, gh, gc, gy);

    // ---- logits + softmax ----
    split_kernel<<<(BT * HH) / 256, 256>>>(gy, gAab, HH, 0);
    split_kernel<<<(VV * HH) / 256, 256>>>(linW, gBbf, HH, 1);
    hgemm<<<gridL, 256>>>(gAab, gBbf, out, linb, (const float*)0, 3 * HH, VV, 0);
    softmax_kernel<<<BT, 256, VV * 4>>>(out, VV);

    (void)in_sizes; (void)n_in; (void)out_size;
}